// round 1
// baseline (speedup 1.0000x reference)
#include <cuda_runtime.h>

// Problem constants (fixed shapes)
#define BB   2
#define NN   2048
#define DD   768
#define HH   12
#define DH   64
#define DP   192
#define NPOS 4095   // 2*N - 1

#define ATT_STRIDE 68  // padded smem row stride (floats) for 64-wide tiles

// ---------------- scratch (device globals; no allocations allowed) ------------
__device__ float g_q[(size_t)BB*HH*NN*DH];     // [b,h,n,d], pre-scaled by 1/8
__device__ float g_k[(size_t)BB*HH*NN*DH];
__device__ float g_v[(size_t)BB*HH*NN*DH];
__device__ float g_vals[(size_t)NPOS*HH];      // DPB MLP output [2N-1, H]
__device__ float g_o[(size_t)BB*NN*DD];        // attention output [b,n,h*64+d]

// =============================================================================
// Kernel 1: QKV projection GEMM.  X[4096,768] @ W[768,2304] + b
// Epilogue scatters into g_q/g_k/g_v with [b,h,n,d] layout; q scaled by 0.125.
// 64x64 tile, BK=16, 256 threads, 4x4 per thread.
// =============================================================================
__global__ __launch_bounds__(256) void qkv_gemm(const float* __restrict__ X,
                                                const float* __restrict__ W,
                                                const float* __restrict__ bias)
{
    __shared__ float As[16][ATT_STRIDE];   // transposed: As[k][m]
    __shared__ float Bs[16][ATT_STRIDE];   // natural:    Bs[k][n]
    const int bm = blockIdx.y * 64;
    const int bn = blockIdx.x * 64;
    const int tid = threadIdx.x;
    const int tx = tid & 15, ty = tid >> 4;
    const int ar = tid >> 2, ac = (tid & 3) << 2;
    const int br = tid >> 4, bc = (tid & 15) << 2;

    float acc[4][4] = {};
    for (int k0 = 0; k0 < 768; k0 += 16) {
        float4 a = *reinterpret_cast<const float4*>(&X[(size_t)(bm + ar) * 768 + k0 + ac]);
        As[ac + 0][ar] = a.x; As[ac + 1][ar] = a.y;
        As[ac + 2][ar] = a.z; As[ac + 3][ar] = a.w;
        *reinterpret_cast<float4*>(&Bs[br][bc]) =
            *reinterpret_cast<const float4*>(&W[(size_t)(k0 + br) * 2304 + bn + bc]);
        __syncthreads();
#pragma unroll
        for (int kk = 0; kk < 16; kk++) {
            float4 av = *reinterpret_cast<const float4*>(&As[kk][ty * 4]);
            float4 bv = *reinterpret_cast<const float4*>(&Bs[kk][tx * 4]);
            float aa[4] = {av.x, av.y, av.z, av.w};
            float bb2[4] = {bv.x, bv.y, bv.z, bv.w};
#pragma unroll
            for (int i = 0; i < 4; i++)
#pragma unroll
                for (int j = 0; j < 4; j++)
                    acc[i][j] = fmaf(aa[i], bb2[j], acc[i][j]);
        }
        __syncthreads();
    }

    const int col0 = bn + tx * 4;
    const int t   = col0 / 768;       // 0=q, 1=k, 2=v  (64-col tiles never straddle)
    const int rem = col0 - t * 768;
    const int h   = rem >> 6;
    const int d0  = rem & 63;
    float* dst = (t == 0) ? g_q : (t == 1) ? g_k : g_v;
    const float sc = (t == 0) ? 0.125f : 1.0f;   // Dh^-0.5 folded into q
    float4 bz = *reinterpret_cast<const float4*>(&bias[col0]);
#pragma unroll
    for (int i = 0; i < 4; i++) {
        int row = bm + ty * 4 + i;
        int b = row >> 11, n = row & 2047;
        float4 o;
        o.x = (acc[i][0] + bz.x) * sc;
        o.y = (acc[i][1] + bz.y) * sc;
        o.z = (acc[i][2] + bz.z) * sc;
        o.w = (acc[i][3] + bz.w) * sc;
        *reinterpret_cast<float4*>(&dst[(((size_t)b * HH + h) * NN + n) * DH + d0]) = o;
    }
}

// =============================================================================
// Kernel 2: DynamicPositionBias MLP, fully fused.  16 rows per block, 192 thr.
// tmp = pre-activation; LN+SiLU -> hbuf; GEMM -> tmp; out layer -> g_vals.
// =============================================================================
__global__ __launch_bounds__(192) void dpb_kernel(const float* __restrict__ w_in,
                                                  const float* __restrict__ b_in,
                                                  const float* __restrict__ w_hid,
                                                  const float* __restrict__ b_hid,
                                                  const float* __restrict__ ln_g,
                                                  const float* __restrict__ ln_b,
                                                  const float* __restrict__ w_out,
                                                  const float* __restrict__ b_out)
{
    __shared__ float hbuf[16][DP];
    __shared__ float tmp[16][DP];
    __shared__ float mu_s[16], rs_s[16];
    const int j    = threadIdx.x;         // 0..191
    const int r0   = blockIdx.x * 16;
    const int warp = j >> 5, lane = j & 31;

    // input layer pre-activation: signed-log positions * w_in + b_in
    const float wi = w_in[j], bi = b_in[j];
#pragma unroll
    for (int r = 0; r < 16; r++) {
        float p = (float)(r0 + r) - 2047.0f;
        float sg = (p > 0.f) ? 1.f : ((p < 0.f) ? -1.f : 0.f);
        float pv = sg * logf(fabsf(p) + 1.f);
        tmp[r][j] = pv * wi + bi;
    }
    __syncthreads();

    for (int layer = 0; layer < 4; layer++) {
        // LayerNorm over each row of tmp, then SiLU -> hbuf
        for (int r = warp; r < 16; r += 6) {
            float s = 0.f, s2 = 0.f;
            for (int k = lane; k < DP; k += 32) {
                float v = tmp[r][k];
                s += v; s2 += v * v;
            }
#pragma unroll
            for (int off = 16; off > 0; off >>= 1) {
                s  += __shfl_xor_sync(0xffffffffu, s,  off);
                s2 += __shfl_xor_sync(0xffffffffu, s2, off);
            }
            if (lane == 0) {
                float mu = s * (1.0f / DP);
                float var = s2 * (1.0f / DP) - mu * mu;
                mu_s[r] = mu;
                rs_s[r] = rsqrtf(var + 1e-5f);
            }
        }
        __syncthreads();
        const float gj = ln_g[layer * DP + j], bj = ln_b[layer * DP + j];
#pragma unroll
        for (int r = 0; r < 16; r++) {
            float v = (tmp[r][j] - mu_s[r]) * rs_s[r] * gj + bj;
            hbuf[r][j] = v / (1.f + expf(-v));    // SiLU
        }
        __syncthreads();

        if (layer < 3) {
            // tmp[r][j] = sum_k hbuf[r][k] * w_hid[layer][k][j] + b_hid[layer][j]
            float acc[16];
#pragma unroll
            for (int r = 0; r < 16; r++) acc[r] = 0.f;
            const float* Wp = w_hid + (size_t)layer * DP * DP + j;
            for (int k = 0; k < DP; k++) {
                float w = Wp[(size_t)k * DP];
#pragma unroll
                for (int r = 0; r < 16; r++) acc[r] = fmaf(hbuf[r][k], w, acc[r]);
            }
            const float bh = b_hid[layer * DP + j];
#pragma unroll
            for (int r = 0; r < 16; r++) tmp[r][j] = acc[r] + bh;
            __syncthreads();
        }
    }

    // output layer: 192 threads -> (row, out-channel) pairs; 16 rows x 12 ch
    const int rr = j / 12, cc = j - rr * 12;
    float a = 0.f;
    for (int k = 0; k < DP; k++) a = fmaf(hbuf[rr][k], w_out[k * 12 + cc], a);
    const int row = r0 + rr;
    if (row < NPOS) g_vals[(size_t)row * HH + cc] = a + b_out[cc];
}

// =============================================================================
// Kernel 3: flash attention with on-the-fly relative position bias.
// Grid: (N/64, B*H).  64 queries/block, 64-key tiles, 256 threads, 4x4 tiles.
// bias[h,i,j] = g_vals[(i-j+N-1)*H + h]; per tile only 127 entries -> smem.
// =============================================================================
__global__ __launch_bounds__(256) void attn_kernel()
{
    extern __shared__ float sm[];
    float* Qs     = sm;                       // [64][68] transposed: Qs[d][m]
    float* Ks     = Qs + 64 * ATT_STRIDE;     // [64][68] transposed: Ks[d][n]
    float* Vs     = Ks + 64 * ATT_STRIDE;     // [64][68] natural:    Vs[k][d]
    float* Ps     = Vs + 64 * ATT_STRIDE;     // [64][68] transposed: Ps[k][m]
    float* vals_s = Ps + 64 * ATT_STRIDE;     // [128] bias diagonal slice

    const int bh = blockIdx.y;
    const int b  = bh / HH, h = bh - b * HH;
    const int q0 = blockIdx.x * 64;
    const float* Qg = g_q + (size_t)bh * NN * DH;
    const float* Kg = g_k + (size_t)bh * NN * DH;
    const float* Vg = g_v + (size_t)bh * NN * DH;

    const int tid = threadIdx.x;
    const int tx = tid & 15, ty = tid >> 4;

    // load Q tile transposed (q already scaled by Dh^-0.5)
#pragma unroll
    for (int i = 0; i < 4; i++) {
        int idx = tid + i * 256;
        int m = idx >> 4;
        int c4 = (idx & 15) << 2;
        float4 v = *reinterpret_cast<const float4*>(&Qg[(size_t)(q0 + m) * DH + c4]);
        Qs[(c4 + 0) * ATT_STRIDE + m] = v.x;
        Qs[(c4 + 1) * ATT_STRIDE + m] = v.y;
        Qs[(c4 + 2) * ATT_STRIDE + m] = v.z;
        Qs[(c4 + 3) * ATT_STRIDE + m] = v.w;
    }

    float m_i[4], l_i[4], oacc[4][4];
#pragma unroll
    for (int i = 0; i < 4; i++) {
        m_i[i] = -1e30f;
        l_i[i] = 0.f;
#pragma unroll
        for (int j = 0; j < 4; j++) oacc[i][j] = 0.f;
    }

    for (int kt = 0; kt < NN / 64; kt++) {
        const int kk0 = kt * 64;
        // stage K (transposed), V (natural), bias slice
#pragma unroll
        for (int i = 0; i < 4; i++) {
            int idx = tid + i * 256;
            int m = idx >> 4;
            int c4 = (idx & 15) << 2;
            float4 kv = *reinterpret_cast<const float4*>(&Kg[(size_t)(kk0 + m) * DH + c4]);
            Ks[(c4 + 0) * ATT_STRIDE + m] = kv.x;
            Ks[(c4 + 1) * ATT_STRIDE + m] = kv.y;
            Ks[(c4 + 2) * ATT_STRIDE + m] = kv.z;
            Ks[(c4 + 3) * ATT_STRIDE + m] = kv.w;
            float4 vv = *reinterpret_cast<const float4*>(&Vg[(size_t)(kk0 + m) * DH + c4]);
            *reinterpret_cast<float4*>(&Vs[m * ATT_STRIDE + c4]) = vv;
        }
        {
            // needed bias indices: (q0+m)-(kk0+n)+2047, m,n in [0,64) -> 127 values
            int base = q0 - kk0 + 2047 - 63;
            if (tid < 127) vals_s[tid] = g_vals[(size_t)(base + tid) * HH + h];
        }
        __syncthreads();

        // S = Q @ K^T   (scale already folded into Q)
        float s[4][4];
#pragma unroll
        for (int i = 0; i < 4; i++)
#pragma unroll
            for (int j = 0; j < 4; j++) s[i][j] = 0.f;
#pragma unroll 8
        for (int d = 0; d < 64; d++) {
            float4 qa = *reinterpret_cast<const float4*>(&Qs[d * ATT_STRIDE + ty * 4]);
            float4 kb = *reinterpret_cast<const float4*>(&Ks[d * ATT_STRIDE + tx * 4]);
            float aa[4] = {qa.x, qa.y, qa.z, qa.w};
            float bb2[4] = {kb.x, kb.y, kb.z, kb.w};
#pragma unroll
            for (int i = 0; i < 4; i++)
#pragma unroll
                for (int j = 0; j < 4; j++)
                    s[i][j] = fmaf(aa[i], bb2[j], s[i][j]);
        }

        // + bias, online softmax update (row groups = 16 threads, shfl width 16)
#pragma unroll
        for (int i = 0; i < 4; i++) {
            int moff = ty * 4 + i - tx * 4 + 63;
#pragma unroll
            for (int j = 0; j < 4; j++) s[i][j] += vals_s[moff - j];
            float rm = fmaxf(fmaxf(s[i][0], s[i][1]), fmaxf(s[i][2], s[i][3]));
#pragma unroll
            for (int off = 8; off > 0; off >>= 1)
                rm = fmaxf(rm, __shfl_xor_sync(0xffffffffu, rm, off, 16));
            float mnew  = fmaxf(m_i[i], rm);
            float alpha = __expf(m_i[i] - mnew);
            float rsum = 0.f;
#pragma unroll
            for (int j = 0; j < 4; j++) {
                float p = __expf(s[i][j] - mnew);
                s[i][j] = p;
                rsum += p;
            }
#pragma unroll
            for (int off = 8; off > 0; off >>= 1)
                rsum += __shfl_xor_sync(0xffffffffu, rsum, off, 16);
            l_i[i] = l_i[i] * alpha + rsum;
            m_i[i] = mnew;
#pragma unroll
            for (int j = 0; j < 4; j++) oacc[i][j] *= alpha;
        }

        // write P transposed for the PV GEMM
#pragma unroll
        for (int i = 0; i < 4; i++)
#pragma unroll
            for (int j = 0; j < 4; j++)
                Ps[(tx * 4 + j) * ATT_STRIDE + ty * 4 + i] = s[i][j];
        __syncthreads();

        // O += P @ V
#pragma unroll 8
        for (int k = 0; k < 64; k++) {
            float4 pa = *reinterpret_cast<const float4*>(&Ps[k * ATT_STRIDE + ty * 4]);
            float4 vb = *reinterpret_cast<const float4*>(&Vs[k * ATT_STRIDE + tx * 4]);
            float aa[4] = {pa.x, pa.y, pa.z, pa.w};
            float bb2[4] = {vb.x, vb.y, vb.z, vb.w};
#pragma unroll
            for (int i = 0; i < 4; i++)
#pragma unroll
                for (int j = 0; j < 4; j++)
                    oacc[i][j] = fmaf(aa[i], bb2[j], oacc[i][j]);
        }
        __syncthreads();
    }

    // normalize and store to [b,n,h*64+d] for the output projection
#pragma unroll
    for (int i = 0; i < 4; i++) {
        float inv = 1.0f / l_i[i];
        float4 o;
        o.x = oacc[i][0] * inv;
        o.y = oacc[i][1] * inv;
        o.z = oacc[i][2] * inv;
        o.w = oacc[i][3] * inv;
        size_t row = (size_t)b * NN + q0 + ty * 4 + i;
        *reinterpret_cast<float4*>(&g_o[row * DD + h * DH + tx * 4]) = o;
    }
}

// =============================================================================
// Kernel 4: output projection.  g_o[4096,768] @ out_w[768,768] + out_b -> out
// =============================================================================
__global__ __launch_bounds__(256) void out_gemm(const float* __restrict__ W,
                                                const float* __restrict__ bias,
                                                float* __restrict__ out)
{
    __shared__ float As[16][ATT_STRIDE];
    __shared__ float Bs[16][ATT_STRIDE];
    const int bm = blockIdx.y * 64;
    const int bn = blockIdx.x * 64;
    const int tid = threadIdx.x;
    const int tx = tid & 15, ty = tid >> 4;
    const int ar = tid >> 2, ac = (tid & 3) << 2;
    const int br = tid >> 4, bc = (tid & 15) << 2;

    float acc[4][4] = {};
    for (int k0 = 0; k0 < 768; k0 += 16) {
        float4 a = *reinterpret_cast<const float4*>(&g_o[(size_t)(bm + ar) * 768 + k0 + ac]);
        As[ac + 0][ar] = a.x; As[ac + 1][ar] = a.y;
        As[ac + 2][ar] = a.z; As[ac + 3][ar] = a.w;
        *reinterpret_cast<float4*>(&Bs[br][bc]) =
            *reinterpret_cast<const float4*>(&W[(size_t)(k0 + br) * 768 + bn + bc]);
        __syncthreads();
#pragma unroll
        for (int kk = 0; kk < 16; kk++) {
            float4 av = *reinterpret_cast<const float4*>(&As[kk][ty * 4]);
            float4 bv = *reinterpret_cast<const float4*>(&Bs[kk][tx * 4]);
            float aa[4] = {av.x, av.y, av.z, av.w};
            float bb2[4] = {bv.x, bv.y, bv.z, bv.w};
#pragma unroll
            for (int i = 0; i < 4; i++)
#pragma unroll
                for (int j = 0; j < 4; j++)
                    acc[i][j] = fmaf(aa[i], bb2[j], acc[i][j]);
        }
        __syncthreads();
    }
    float4 bz = *reinterpret_cast<const float4*>(&bias[bn + tx * 4]);
#pragma unroll
    for (int i = 0; i < 4; i++) {
        int row = bm + ty * 4 + i;
        float4 o;
        o.x = acc[i][0] + bz.x;
        o.y = acc[i][1] + bz.y;
        o.z = acc[i][2] + bz.z;
        o.w = acc[i][3] + bz.w;
        *reinterpret_cast<float4*>(&out[(size_t)row * 768 + bn + tx * 4]) = o;
    }
}

// =============================================================================
extern "C" void kernel_launch(void* const* d_in, const int* in_sizes, int n_in,
                              void* d_out, int out_size)
{
    const float* x         = (const float*)d_in[0];
    const float* qkv_w     = (const float*)d_in[1];
    const float* qkv_b     = (const float*)d_in[2];
    const float* out_w     = (const float*)d_in[3];
    const float* out_b     = (const float*)d_in[4];
    const float* dpb_w_in  = (const float*)d_in[5];
    const float* dpb_b_in  = (const float*)d_in[6];
    const float* dpb_w_hid = (const float*)d_in[7];
    const float* dpb_b_hid = (const float*)d_in[8];
    const float* dpb_ln_g  = (const float*)d_in[9];
    const float* dpb_ln_b  = (const float*)d_in[10];
    const float* dpb_w_out = (const float*)d_in[11];
    const float* dpb_b_out = (const float*)d_in[12];
    float* out = (float*)d_out;

    const int attn_smem = (4 * 64 * ATT_STRIDE + 128) * (int)sizeof(float);  // ~70 KB
    cudaFuncSetAttribute(attn_kernel, cudaFuncAttributeMaxDynamicSharedMemorySize,
                         attn_smem);

    dpb_kernel<<<256, 192>>>(dpb_w_in, dpb_b_in, dpb_w_hid, dpb_b_hid,
                             dpb_ln_g, dpb_ln_b, dpb_w_out, dpb_b_out);
    qkv_gemm<<<dim3(36, 64), 256>>>(x, qkv_w, qkv_b);
    attn_kernel<<<dim3(32, 24), 256, attn_smem>>>();
    out_gemm<<<dim3(12, 64), 256>>>(out_w, out_b, out);
}